// round 2
// baseline (speedup 1.0000x reference)
#include <cuda_runtime.h>

#define LQ 4096
#define BB 8
#define DM 1024
#define NH 16
#define DH 64
#define NS 128

// Scratch (static device globals — allocation-free per harness rules)
__device__ float g_qp[(size_t)BB * NH * LQ * DH];   // [b][h][i][dh]
__device__ float g_kp[BB * NH * NS * DH];           // [b][h][s][dh]
__device__ float g_vp[BB * NH * NS * DH];
__device__ float g_ctx[(size_t)LQ * BB * DM];       // [i*B+b][D]
__device__ int   g_sidx[NS];
__device__ int   g_mkl[BB];

// ---------------------------------------------------------------------------
// Setup: normalize sampled_index / key_length (int32 or int64 on the wire),
// compute mkl[b] = #{s : sidx[s] < key_length[b]}.
// Detection: if stored as int64 little-endian, the 2nd int32 word is the high
// word of element 0 (== 0). If int32, it is sidx[1] in [32,64) / klen[1] >= 2048,
// both nonzero. Unambiguous.
// ---------------------------------------------------------------------------
__global__ void setup_kernel(const void* sidx_raw, const void* klen_raw)
{
    __shared__ int s_sidx[NS];
    __shared__ int s_klen[BB];
    int t = threadIdx.x;  // 128 threads

    const int* si = (const int*)sidx_raw;
    int sv;
    if (si[1] == 0) sv = (int)((const long long*)sidx_raw)[t];
    else            sv = si[t];
    s_sidx[t] = sv;
    g_sidx[t] = sv;

    if (t < BB) {
        const int* ki = (const int*)klen_raw;
        int kv;
        if (ki[1] == 0) kv = (int)((const long long*)klen_raw)[t];
        else            kv = ki[t];
        s_klen[t] = kv;
    }
    __syncthreads();
    if (t < BB) {
        int c = 0;
        for (int s = 0; s < NS; s++) c += (s_sidx[s] < s_klen[t]) ? 1 : 0;
        g_mkl[t] = c;
    }
}

// ---------------------------------------------------------------------------
// Tiled SGEMM, C = A * W^T + bias  (both A and W row-major with K contiguous).
// BM=BN=128, BK=16, 256 threads, 8x8 register tile per thread.
// AMODE: 0 = A direct (row r -> A + r*K)
//        1 = gather:  r = s*B+b -> A + (sidx[s]*B+b)*K
//        2 = A is g_ctx
// CMODE: 0 = C[row*N+col] (param C)
//        1 = scatter to g_qp [b][h][i][dh]
//        2 = scatter to g_kp [b][h][s][dh]
//        3 = scatter to g_vp [b][h][s][dh]
// ---------------------------------------------------------------------------
template <int AMODE, int CMODE>
__global__ void __launch_bounds__(256)
sgemm_nt(const float* __restrict__ A, const float* __restrict__ W,
         const float* __restrict__ bias, float* __restrict__ C,
         int M, int N, int K)
{
    __shared__ float As[16][128];
    __shared__ float Bs[16][128];

    const int tid = threadIdx.x;
    const int bm = blockIdx.y * 128;
    const int bn = blockIdx.x * 128;
    const int lr = tid >> 2;          // 0..63 loader row
    const int lk = (tid & 3) << 2;    // 0,4,8,12 loader k-offset

    const float* arow0;
    const float* arow1;
    {
        int r0 = bm + lr, r1 = r0 + 64;
        if (AMODE == 0) {
            arow0 = A + (size_t)r0 * K;
            arow1 = A + (size_t)r1 * K;
        } else if (AMODE == 1) {
            arow0 = A + (size_t)(g_sidx[r0 >> 3] * BB + (r0 & 7)) * K;
            arow1 = A + (size_t)(g_sidx[r1 >> 3] * BB + (r1 & 7)) * K;
        } else {
            arow0 = g_ctx + (size_t)r0 * K;
            arow1 = g_ctx + (size_t)r1 * K;
        }
    }
    const float* wrow0 = W + (size_t)(bn + lr) * K;
    const float* wrow1 = W + (size_t)(bn + lr + 64) * K;

    const int trow = (tid >> 4) << 3;   // 0..120
    const int tcol = (tid & 15) << 3;   // 0..120

    float acc[8][8];
#pragma unroll
    for (int i = 0; i < 8; i++)
#pragma unroll
        for (int j = 0; j < 8; j++) acc[i][j] = 0.f;

    for (int kt = 0; kt < K; kt += 16) {
        float4 a0 = *(const float4*)(arow0 + kt + lk);
        float4 a1 = *(const float4*)(arow1 + kt + lk);
        float4 w0 = *(const float4*)(wrow0 + kt + lk);
        float4 w1 = *(const float4*)(wrow1 + kt + lk);
        __syncthreads();
        As[lk + 0][lr] = a0.x; As[lk + 1][lr] = a0.y; As[lk + 2][lr] = a0.z; As[lk + 3][lr] = a0.w;
        As[lk + 0][lr + 64] = a1.x; As[lk + 1][lr + 64] = a1.y; As[lk + 2][lr + 64] = a1.z; As[lk + 3][lr + 64] = a1.w;
        Bs[lk + 0][lr] = w0.x; Bs[lk + 1][lr] = w0.y; Bs[lk + 2][lr] = w0.z; Bs[lk + 3][lr] = w0.w;
        Bs[lk + 0][lr + 64] = w1.x; Bs[lk + 1][lr + 64] = w1.y; Bs[lk + 2][lr + 64] = w1.z; Bs[lk + 3][lr + 64] = w1.w;
        __syncthreads();
#pragma unroll
        for (int kk = 0; kk < 16; kk++) {
            float4 av0 = *(const float4*)&As[kk][trow];
            float4 av1 = *(const float4*)&As[kk][trow + 4];
            float4 bv0 = *(const float4*)&Bs[kk][tcol];
            float4 bv1 = *(const float4*)&Bs[kk][tcol + 4];
            float ar[8] = {av0.x, av0.y, av0.z, av0.w, av1.x, av1.y, av1.z, av1.w};
            float br[8] = {bv0.x, bv0.y, bv0.z, bv0.w, bv1.x, bv1.y, bv1.z, bv1.w};
#pragma unroll
            for (int i = 0; i < 8; i++)
#pragma unroll
                for (int j = 0; j < 8; j++)
                    acc[i][j] = fmaf(ar[i], br[j], acc[i][j]);
        }
    }

#pragma unroll
    for (int i = 0; i < 8; i++) {
        int row = bm + trow + i;
        if (row >= M) continue;
#pragma unroll
        for (int j = 0; j < 8; j++) {
            int col = bn + tcol + j;
            if (col >= N) continue;
            float vv = acc[i][j] + bias[col];
            if (CMODE == 0) {
                C[(size_t)row * N + col] = vv;
            } else if (CMODE == 1) {
                int i_ = row >> 3, b_ = row & 7, h_ = col >> 6, d_ = col & 63;
                g_qp[(((size_t)(b_ * NH + h_)) * LQ + i_) * DH + d_] = vv;
            } else if (CMODE == 2) {
                int s_ = row >> 3, b_ = row & 7, h_ = col >> 6, d_ = col & 63;
                g_kp[((b_ * NH + h_) * NS + s_) * DH + d_] = vv;
            } else {
                int s_ = row >> 3, b_ = row & 7, h_ = col >> 6, d_ = col & 63;
                g_vp[((b_ * NH + h_) * NS + s_) * DH + d_] = vv;
            }
        }
    }
}

// ---------------------------------------------------------------------------
// Fused attention: grid (L/128, B*H), 128 threads; each thread = 1 query row.
// kp then vp staged in SMEM (broadcast reads), per-thread scores row in padded
// SMEM (stride 129 -> conflict-free), softmax over valid prefix.
// Valid keys per (i,b) = prefix of length min(mkl[b], #{sidx <= i}).
// ---------------------------------------------------------------------------
__global__ void __launch_bounds__(128)
attn_kernel()
{
    extern __shared__ float smem[];
    float* s_kv = smem;                       // NS*DH = 8192 floats
    float* s_sc = smem + NS * DH;             // 128*129 floats
    int*   s_si = (int*)(smem + NS * DH + 128 * 129);

    const int ti = threadIdx.x;
    const int bh = blockIdx.y;                // b*NH + h
    const int b  = bh >> 4;
    const int h  = bh & 15;
    const int qi = blockIdx.x * 128 + ti;

    s_si[ti] = g_sidx[ti];

    const float4* kp4 = (const float4*)(g_kp + (size_t)bh * NS * DH);
#pragma unroll
    for (int x = ti; x < NS * DH / 4; x += 128)
        ((float4*)s_kv)[x] = kp4[x];
    __syncthreads();

    const int mkl = g_mkl[b];
    int lo = 0, hi = NS;
    while (lo < hi) { int mid = (lo + hi) >> 1; if (s_si[mid] <= qi) lo = mid + 1; else hi = mid; }
    const int nv = min(mkl, lo);              // >= 1 always (sidx[0]==0)

    float qr[DH];
    const float4* qrow = (const float4*)(g_qp + ((size_t)bh * LQ + qi) * DH);
#pragma unroll
    for (int d4 = 0; d4 < DH / 4; d4++) {
        float4 t = qrow[d4];
        qr[4 * d4] = t.x; qr[4 * d4 + 1] = t.y; qr[4 * d4 + 2] = t.z; qr[4 * d4 + 3] = t.w;
    }

    float* myrow = s_sc + ti * 129;
    float m = -1e30f;
    for (int s = 0; s < nv; s++) {
        const float4* kr = (const float4*)(s_kv + s * DH);
        float dot = 0.f;
#pragma unroll
        for (int d4 = 0; d4 < DH / 4; d4++) {
            float4 kv = kr[d4];
            dot = fmaf(qr[4 * d4], kv.x, dot);
            dot = fmaf(qr[4 * d4 + 1], kv.y, dot);
            dot = fmaf(qr[4 * d4 + 2], kv.z, dot);
            dot = fmaf(qr[4 * d4 + 3], kv.w, dot);
        }
        dot *= 0.125f;                        // 1/sqrt(64)
        myrow[s] = dot;
        m = fmaxf(m, dot);
    }
    float sum = 0.f;
    for (int s = 0; s < nv; s++) {
        float p = __expf(myrow[s] - m);
        myrow[s] = p;
        sum += p;
    }
    const float inv = 1.0f / sum;
    __syncthreads();                          // everyone done reading kp

    const float4* vp4 = (const float4*)(g_vp + (size_t)bh * NS * DH);
#pragma unroll
    for (int x = ti; x < NS * DH / 4; x += 128)
        ((float4*)s_kv)[x] = vp4[x];
    __syncthreads();

    float acc[DH];
#pragma unroll
    for (int d = 0; d < DH; d++) acc[d] = 0.f;
    for (int s = 0; s < nv; s++) {
        float p = myrow[s];
        const float4* vr = (const float4*)(s_kv + s * DH);
#pragma unroll
        for (int d4 = 0; d4 < DH / 4; d4++) {
            float4 vv = vr[d4];
            acc[4 * d4]     = fmaf(p, vv.x, acc[4 * d4]);
            acc[4 * d4 + 1] = fmaf(p, vv.y, acc[4 * d4 + 1]);
            acc[4 * d4 + 2] = fmaf(p, vv.z, acc[4 * d4 + 2]);
            acc[4 * d4 + 3] = fmaf(p, vv.w, acc[4 * d4 + 3]);
        }
    }
    float4* crow = (float4*)(g_ctx + ((size_t)qi * BB + b) * DM + h * DH);
#pragma unroll
    for (int d4 = 0; d4 < DH / 4; d4++) {
        float4 o;
        o.x = acc[4 * d4] * inv;     o.y = acc[4 * d4 + 1] * inv;
        o.z = acc[4 * d4 + 2] * inv; o.w = acc[4 * d4 + 3] * inv;
        crow[d4] = o;
    }
}

static const int ATTN_SMEM = (NS * DH + 128 * 129) * 4 + NS * 4;  // 99328 B

extern "C" void kernel_launch(void* const* d_in, const int* in_sizes, int n_in,
                              void* d_out, int out_size)
{
    const float* q    = (const float*)d_in[0];
    const float* k    = (const float*)d_in[1];
    const float* v    = (const float*)d_in[2];
    const void*  klen = d_in[3];
    const void*  sidx = d_in[4];
    const float* ipw  = (const float*)d_in[5];   // [3D, D]
    const float* ipb  = (const float*)d_in[6];   // [3D]
    const float* ow   = (const float*)d_in[7];   // [D, D]
    const float* ob   = (const float*)d_in[8];   // [D]
    float* out = (float*)d_out;

    (void)in_sizes; (void)n_in; (void)out_size;

    cudaFuncSetAttribute(attn_kernel, cudaFuncAttributeMaxDynamicSharedMemorySize, ATTN_SMEM);

    setup_kernel<<<1, 128>>>(sidx, klen);

    // k/v projections with bucket gather: M = S*B = 1024
    {
        dim3 g(DM / 128, (NS * BB) / 128);   // (8, 8)
        sgemm_nt<1, 2><<<g, 256>>>(k, ipw + (size_t)DM * DM,     ipb + DM,     nullptr, NS * BB, DM, DM);
        sgemm_nt<1, 3><<<g, 256>>>(v, ipw + (size_t)2 * DM * DM, ipb + 2 * DM, nullptr, NS * BB, DM, DM);
    }
    // q projection: M = L*B = 32768
    {
        dim3 g(DM / 128, (LQ * BB) / 128);   // (8, 256)
        sgemm_nt<0, 1><<<g, 256>>>(q, ipw, ipb, nullptr, LQ * BB, DM, DM);
    }
    // fused masked attention
    {
        dim3 g(LQ / 128, BB * NH);           // (32, 128)
        attn_kernel<<<g, 128, ATTN_SMEM>>>();
    }
    // output projection
    {
        dim3 g(DM / 128, (LQ * BB) / 128);   // (8, 256)
        sgemm_nt<2, 0><<<g, 256>>>(nullptr, ow, ob, out, LQ * BB, DM, DM);
    }
}

// round 7
// speedup vs baseline: 2.7808x; 2.7808x over previous
#include <cuda_runtime.h>
#include <cstdint>

#define LQ 4096
#define BB 8
#define DM 1024
#define NH 16
#define DH 64
#define NS 128

// Scratch (static device globals — allocation-free per harness rules)
__device__ float g_qp[(size_t)BB * NH * LQ * DH];   // [b][h][i][dh]
__device__ float g_kp[BB * NH * NS * DH];           // [b][h][s][dh]
__device__ float g_vp[BB * NH * NS * DH];
__device__ float g_ctx[(size_t)LQ * BB * DM];       // [i*B+b][D]
__device__ int   g_sidx[NS];
__device__ int   g_mkl[BB];

// ---------------------------------------------------------------------------
// Setup: normalize sampled_index / key_length (int32 or int64 on the wire).
// ---------------------------------------------------------------------------
__global__ void setup_kernel(const void* sidx_raw, const void* klen_raw)
{
    __shared__ int s_sidx[NS];
    __shared__ int s_klen[BB];
    int t = threadIdx.x;  // 128 threads

    const int* si = (const int*)sidx_raw;
    int sv;
    if (si[1] == 0) sv = (int)((const long long*)sidx_raw)[t];
    else            sv = si[t];
    s_sidx[t] = sv;
    g_sidx[t] = sv;

    if (t < BB) {
        const int* ki = (const int*)klen_raw;
        int kv;
        if (ki[1] == 0) kv = (int)((const long long*)klen_raw)[t];
        else            kv = ki[t];
        s_klen[t] = kv;
    }
    __syncthreads();
    if (t < BB) {
        int c = 0;
        for (int s = 0; s < NS; s++) c += (s_sidx[s] < s_klen[t]) ? 1 : 0;
        g_mkl[t] = c;
    }
}

// ---------------------------------------------------------------------------
// TF32 tensor-core GEMM:  C = A * W^T + bias
// Block tile 128x128x32, 128 threads (4 warps, each 64x64), double-buffered
// smem via cp.async.cg, mma.sync.aligned.m16n8k8.row.col.f32.tf32.
// Smem layout: padded rows of 36 floats -> conflict-free frag loads.
// AMODE: 0 = direct rows, 1 = bucket gather (sidx), 2 = A is g_ctx
// CMODE: 0 = C[row*N+col], 1 = scatter g_qp, 2 = g_kp, 3 = g_vp
// All dims are multiples of 128 -> no bounds checks.
// ---------------------------------------------------------------------------
#define BKK 32
#define ROWPAD 36
#define A_STAGE (128 * ROWPAD)          // floats per stage buffer

__device__ __forceinline__ uint32_t f2tf32(float x) {
    uint32_t u;
    asm volatile("cvt.rna.tf32.f32 %0, %1;\n" : "=r"(u) : "f"(x));
    return u;
}

__device__ __forceinline__ void mma_tf32(float4& d, const uint32_t a[4], const uint32_t b[2]) {
    asm volatile(
        "mma.sync.aligned.m16n8k8.row.col.f32.tf32.tf32.f32 "
        "{%0,%1,%2,%3}, {%4,%5,%6,%7}, {%8,%9}, {%0,%1,%2,%3};\n"
        : "+f"(d.x), "+f"(d.y), "+f"(d.z), "+f"(d.w)
        : "r"(a[0]), "r"(a[1]), "r"(a[2]), "r"(a[3]), "r"(b[0]), "r"(b[1]));
}

__device__ __forceinline__ uint32_t smem_u32(const void* p) {
    return (uint32_t)__cvta_generic_to_shared(p);
}

template <int AMODE, int CMODE>
__global__ void __launch_bounds__(128)
tgemm_nt(const float* __restrict__ A, const float* __restrict__ W,
         const float* __restrict__ bias, float* __restrict__ C,
         int M, int N, int K)
{
    extern __shared__ float sm[];
    float* smA = sm;                      // [2][128][36]
    float* smB = sm + 2 * A_STAGE;        // [2][128][36]

    const int tid  = threadIdx.x;
    const int lane = tid & 31;
    const int wid  = tid >> 5;            // 0..3
    const int wm   = wid & 1;             // warp row (2)
    const int wn   = wid >> 1;            // warp col (2)
    const int g    = lane >> 2;           // 0..7
    const int tig  = lane & 3;            // 0..3

    const int bm = blockIdx.y * 128;
    const int bn = blockIdx.x * 128;

    // --- per-thread loader geometry: 8 float4 per operand per stage ---
    const int lrow = tid >> 3;            // 0..15  (row within 16-row slab)
    const int lc4  = (tid & 7) * 4;       // 0,4,...,28  (k offset)

    const float* aptr[8];
    const float* wptr[8];
#pragma unroll
    for (int j = 0; j < 8; j++) {
        int r = j * 16 + lrow;            // 0..127 row within tile
        int grow = bm + r;
        if (AMODE == 0)      aptr[j] = A + (size_t)grow * K + lc4;
        else if (AMODE == 1) aptr[j] = A + (size_t)(g_sidx[grow >> 3] * BB + (grow & 7)) * K + lc4;
        else                 aptr[j] = g_ctx + (size_t)grow * K + lc4;
        wptr[j] = W + (size_t)(bn + r) * K + lc4;
    }
    const uint32_t sdstA = smem_u32(smA + lrow * ROWPAD + lc4);  // + j*16*ROWPAD + buf*A_STAGE
    const uint32_t sdstB = smem_u32(smB + lrow * ROWPAD + lc4);

    float4 acc[4][8];
#pragma unroll
    for (int i = 0; i < 4; i++)
#pragma unroll
        for (int j = 0; j < 8; j++) acc[i][j] = make_float4(0.f, 0.f, 0.f, 0.f);

    const int nk = K / BKK;

    // prologue: stage 0
#pragma unroll
    for (int j = 0; j < 8; j++) {
        asm volatile("cp.async.cg.shared.global [%0], [%1], 16;\n"
                     :: "r"(sdstA + (uint32_t)(j * 16 * ROWPAD * 4)), "l"(aptr[j]));
        asm volatile("cp.async.cg.shared.global [%0], [%1], 16;\n"
                     :: "r"(sdstB + (uint32_t)(j * 16 * ROWPAD * 4)), "l"(wptr[j]));
    }
    asm volatile("cp.async.commit_group;\n");

    for (int kt = 0; kt < nk; kt++) {
        if (kt + 1 < nk) {
            uint32_t bofs = (uint32_t)(((kt + 1) & 1) * A_STAGE * 4);
            int gofs = (kt + 1) * BKK;
#pragma unroll
            for (int j = 0; j < 8; j++) {
                asm volatile("cp.async.cg.shared.global [%0], [%1], 16;\n"
                             :: "r"(sdstA + bofs + (uint32_t)(j * 16 * ROWPAD * 4)),
                                "l"(aptr[j] + gofs));
                asm volatile("cp.async.cg.shared.global [%0], [%1], 16;\n"
                             :: "r"(sdstB + bofs + (uint32_t)(j * 16 * ROWPAD * 4)),
                                "l"(wptr[j] + gofs));
            }
            asm volatile("cp.async.commit_group;\n");
            asm volatile("cp.async.wait_group 1;\n" ::: "memory");
        } else {
            asm volatile("cp.async.wait_group 0;\n" ::: "memory");
        }
        __syncthreads();

        const float* Ab = smA + (kt & 1) * A_STAGE;
        const float* Bb = smB + (kt & 1) * A_STAGE;

#pragma unroll
        for (int ks = 0; ks < 4; ks++) {
            const int k0 = ks * 8 + tig;
            uint32_t afr[4][4];
            uint32_t bfr[8][2];
#pragma unroll
            for (int mt = 0; mt < 4; mt++) {
                int r = wm * 64 + mt * 16 + g;
                afr[mt][0] = f2tf32(Ab[r * ROWPAD + k0]);
                afr[mt][1] = f2tf32(Ab[(r + 8) * ROWPAD + k0]);
                afr[mt][2] = f2tf32(Ab[r * ROWPAD + k0 + 4]);
                afr[mt][3] = f2tf32(Ab[(r + 8) * ROWPAD + k0 + 4]);
            }
#pragma unroll
            for (int nt = 0; nt < 8; nt++) {
                int n = wn * 64 + nt * 8 + g;
                bfr[nt][0] = f2tf32(Bb[n * ROWPAD + k0]);
                bfr[nt][1] = f2tf32(Bb[n * ROWPAD + k0 + 4]);
            }
#pragma unroll
            for (int mt = 0; mt < 4; mt++)
#pragma unroll
                for (int nt = 0; nt < 8; nt++)
                    mma_tf32(acc[mt][nt], afr[mt], bfr[nt]);
        }
        __syncthreads();
    }

    // --- epilogue ---
#pragma unroll
    for (int nt = 0; nt < 8; nt++) {
        int col = bn + wn * 64 + nt * 8 + tig * 2;
        float b0 = bias[col], b1 = bias[col + 1];
#pragma unroll
        for (int mt = 0; mt < 4; mt++) {
            int row = bm + wm * 64 + mt * 16 + g;
            float2 v0 = make_float2(acc[mt][nt].x + b0, acc[mt][nt].y + b1);
            float2 v1 = make_float2(acc[mt][nt].z + b0, acc[mt][nt].w + b1);
            if (CMODE == 0) {
                *(float2*)(C + (size_t)row * N + col) = v0;
                *(float2*)(C + (size_t)(row + 8) * N + col) = v1;
            } else if (CMODE == 1) {
                int h_ = col >> 6, d_ = col & 63;
                int i0 = row >> 3, b_ = row & 7;
                *(float2*)(g_qp + (((size_t)(b_ * NH + h_)) * LQ + i0) * DH + d_) = v0;
                int i1 = (row + 8) >> 3;   // b_ unchanged (+8 rows = +1 i)
                *(float2*)(g_qp + (((size_t)(b_ * NH + h_)) * LQ + i1) * DH + d_) = v1;
            } else if (CMODE == 2) {
                int h_ = col >> 6, d_ = col & 63;
                int s0 = row >> 3, b_ = row & 7;
                *(float2*)(g_kp + ((b_ * NH + h_) * NS + s0) * DH + d_) = v0;
                int s1 = (row + 8) >> 3;
                *(float2*)(g_kp + ((b_ * NH + h_) * NS + s1) * DH + d_) = v1;
            } else {
                int h_ = col >> 6, d_ = col & 63;
                int s0 = row >> 3, b_ = row & 7;
                *(float2*)(g_vp + ((b_ * NH + h_) * NS + s0) * DH + d_) = v0;
                int s1 = (row + 8) >> 3;
                *(float2*)(g_vp + ((b_ * NH + h_) * NS + s1) * DH + d_) = v1;
            }
        }
    }
}

static const int GEMM_SMEM = 4 * A_STAGE * 4;   // 73728 B

// ---------------------------------------------------------------------------
// Fused attention (unchanged from R2): grid (L/128, B*H), 128 threads.
// ---------------------------------------------------------------------------
__global__ void __launch_bounds__(128)
attn_kernel()
{
    extern __shared__ float smem[];
    float* s_kv = smem;                       // NS*DH = 8192 floats
    float* s_sc = smem + NS * DH;             // 128*129 floats
    int*   s_si = (int*)(smem + NS * DH + 128 * 129);

    const int ti = threadIdx.x;
    const int bh = blockIdx.y;                // b*NH + h
    const int b  = bh >> 4;
    const int h  = bh & 15;
    const int qi = blockIdx.x * 128 + ti;

    s_si[ti] = g_sidx[ti];

    const float4* kp4 = (const float4*)(g_kp + (size_t)bh * NS * DH);
#pragma unroll
    for (int x = ti; x < NS * DH / 4; x += 128)
        ((float4*)s_kv)[x] = kp4[x];
    __syncthreads();

    const int mkl = g_mkl[b];
    int lo = 0, hi = NS;
    while (lo < hi) { int mid = (lo + hi) >> 1; if (s_si[mid] <= qi) lo = mid + 1; else hi = mid; }
    const int nv = min(mkl, lo);              // >= 1 always (sidx[0]==0)

    float qr[DH];
    const float4* qrow = (const float4*)(g_qp + ((size_t)bh * LQ + qi) * DH);
#pragma unroll
    for (int d4 = 0; d4 < DH / 4; d4++) {
        float4 t = qrow[d4];
        qr[4 * d4] = t.x; qr[4 * d4 + 1] = t.y; qr[4 * d4 + 2] = t.z; qr[4 * d4 + 3] = t.w;
    }

    float* myrow = s_sc + ti * 129;
    float m = -1e30f;
    for (int s = 0; s < nv; s++) {
        const float4* kr = (const float4*)(s_kv + s * DH);
        float dot = 0.f;
#pragma unroll
        for (int d4 = 0; d4 < DH / 4; d4++) {
            float4 kv = kr[d4];
            dot = fmaf(qr[4 * d4], kv.x, dot);
            dot = fmaf(qr[4 * d4 + 1], kv.y, dot);
            dot = fmaf(qr[4 * d4 + 2], kv.z, dot);
            dot = fmaf(qr[4 * d4 + 3], kv.w, dot);
        }
        dot *= 0.125f;                        // 1/sqrt(64)
        myrow[s] = dot;
        m = fmaxf(m, dot);
    }
    float sum = 0.f;
    for (int s = 0; s < nv; s++) {
        float p = __expf(myrow[s] - m);
        myrow[s] = p;
        sum += p;
    }
    const float inv = 1.0f / sum;
    __syncthreads();                          // everyone done reading kp

    const float4* vp4 = (const float4*)(g_vp + (size_t)bh * NS * DH);
#pragma unroll
    for (int x = ti; x < NS * DH / 4; x += 128)
        ((float4*)s_kv)[x] = vp4[x];
    __syncthreads();

    float acc[DH];
#pragma unroll
    for (int d = 0; d < DH; d++) acc[d] = 0.f;
    for (int s = 0; s < nv; s++) {
        float p = myrow[s];
        const float4* vr = (const float4*)(s_kv + s * DH);
#pragma unroll
        for (int d4 = 0; d4 < DH / 4; d4++) {
            float4 vv = vr[d4];
            acc[4 * d4]     = fmaf(p, vv.x, acc[4 * d4]);
            acc[4 * d4 + 1] = fmaf(p, vv.y, acc[4 * d4 + 1]);
            acc[4 * d4 + 2] = fmaf(p, vv.z, acc[4 * d4 + 2]);
            acc[4 * d4 + 3] = fmaf(p, vv.w, acc[4 * d4 + 3]);
        }
    }
    float4* crow = (float4*)(g_ctx + ((size_t)qi * BB + b) * DM + h * DH);
#pragma unroll
    for (int d4 = 0; d4 < DH / 4; d4++) {
        float4 o;
        o.x = acc[4 * d4] * inv;     o.y = acc[4 * d4 + 1] * inv;
        o.z = acc[4 * d4 + 2] * inv; o.w = acc[4 * d4 + 3] * inv;
        crow[d4] = o;
    }
}

static const int ATTN_SMEM = (NS * DH + 128 * 129) * 4 + NS * 4;  // 99328 B

extern "C" void kernel_launch(void* const* d_in, const int* in_sizes, int n_in,
                              void* d_out, int out_size)
{
    const float* q    = (const float*)d_in[0];
    const float* k    = (const float*)d_in[1];
    const float* v    = (const float*)d_in[2];
    const void*  klen = d_in[3];
    const void*  sidx = d_in[4];
    const float* ipw  = (const float*)d_in[5];   // [3D, D]
    const float* ipb  = (const float*)d_in[6];   // [3D]
    const float* ow   = (const float*)d_in[7];   // [D, D]
    const float* ob   = (const float*)d_in[8];   // [D]
    float* out = (float*)d_out;

    (void)in_sizes; (void)n_in; (void)out_size;

    cudaFuncSetAttribute(attn_kernel, cudaFuncAttributeMaxDynamicSharedMemorySize, ATTN_SMEM);
    cudaFuncSetAttribute(tgemm_nt<0, 1>, cudaFuncAttributeMaxDynamicSharedMemorySize, GEMM_SMEM);
    cudaFuncSetAttribute(tgemm_nt<1, 2>, cudaFuncAttributeMaxDynamicSharedMemorySize, GEMM_SMEM);
    cudaFuncSetAttribute(tgemm_nt<1, 3>, cudaFuncAttributeMaxDynamicSharedMemorySize, GEMM_SMEM);
    cudaFuncSetAttribute(tgemm_nt<2, 0>, cudaFuncAttributeMaxDynamicSharedMemorySize, GEMM_SMEM);

    setup_kernel<<<1, 128>>>(sidx, klen);

    // k/v projections with bucket gather: M = S*B = 1024
    {
        dim3 g(DM / 128, (NS * BB) / 128);   // (8, 8)
        tgemm_nt<1, 2><<<g, 128, GEMM_SMEM>>>(k, ipw + (size_t)DM * DM,     ipb + DM,     nullptr, NS * BB, DM, DM);
        tgemm_nt<1, 3><<<g, 128, GEMM_SMEM>>>(v, ipw + (size_t)2 * DM * DM, ipb + 2 * DM, nullptr, NS * BB, DM, DM);
    }
    // q projection: M = L*B = 32768
    {
        dim3 g(DM / 128, (LQ * BB) / 128);   // (8, 256)
        tgemm_nt<0, 1><<<g, 128, GEMM_SMEM>>>(q, ipw, ipb, nullptr, LQ * BB, DM, DM);
    }
    // fused masked attention
    {
        dim3 g(LQ / 128, BB * NH);           // (32, 128)
        attn_kernel<<<g, 128, ATTN_SMEM>>>();
    }
    // output projection
    {
        dim3 g(DM / 128, (LQ * BB) / 128);   // (8, 256)
        tgemm_nt<2, 0><<<g, 128, GEMM_SMEM>>>(nullptr, ow, ob, out, LQ * BB, DM, DM);
    }
}

// round 10
// speedup vs baseline: 2.8803x; 1.0358x over previous
#include <cuda_runtime.h>
#include <cstdint>

#define LQ 4096
#define BB 8
#define DM 1024
#define NH 16
#define DH 64
#define NS 128

// ---------------------------------------------------------------------------
// Scratch (static device globals — allocation-free per harness rules)
// ---------------------------------------------------------------------------
__device__ float g_qp[(size_t)BB * NH * LQ * DH];   // [b][h][i][dh]
__device__ float g_kp[BB * NH * NS * DH];           // [b][h][s][dh]
__device__ float g_vp[BB * NH * NS * DH];
__device__ float g_ctx[(size_t)LQ * BB * DM];       // [i*B+b][D]  (tf32-rounded)
__device__ float g_qr[(size_t)LQ * BB * DM];        // tf32-rounded q
__device__ float g_kg[NS * BB * DM];                // gathered+rounded k rows
__device__ float g_vg[NS * BB * DM];
__device__ float g_wr[3 * DM * DM];                 // tf32-rounded in_proj_weight
__device__ float g_owr[DM * DM];                    // tf32-rounded out_w
__device__ int   g_sidx[NS];
__device__ int   g_mkl[BB];

__device__ __forceinline__ uint32_t smem_u32(const void* p) {
    return (uint32_t)__cvta_generic_to_shared(p);
}
__device__ __forceinline__ float tf32r(float x) {   // round-to-nearest tf32
    uint32_t u;
    asm volatile("cvt.rna.tf32.f32 %0, %1;\n" : "=r"(u) : "f"(x));
    return __uint_as_float(u);
}
__device__ __forceinline__ void mma_tf32(float4& d, const uint32_t a[4], const uint32_t b[2]) {
    asm volatile(
        "mma.sync.aligned.m16n8k8.row.col.f32.tf32.tf32.f32 "
        "{%0,%1,%2,%3}, {%4,%5,%6,%7}, {%8,%9}, {%0,%1,%2,%3};\n"
        : "+f"(d.x), "+f"(d.y), "+f"(d.z), "+f"(d.w)
        : "r"(a[0]), "r"(a[1]), "r"(a[2]), "r"(a[3]), "r"(b[0]), "r"(b[1]));
}

// ---------------------------------------------------------------------------
// Setup: normalize sampled_index / key_length (int32 or int64 on the wire).
// ---------------------------------------------------------------------------
__global__ void setup_kernel(const void* sidx_raw, const void* klen_raw)
{
    __shared__ int s_sidx[NS];
    __shared__ int s_klen[BB];
    int t = threadIdx.x;  // 128 threads

    const int* si = (const int*)sidx_raw;
    int sv;
    if (si[1] == 0) sv = (int)((const long long*)sidx_raw)[t];
    else            sv = si[t];
    s_sidx[t] = sv;
    g_sidx[t] = sv;

    if (t < BB) {
        const int* ki = (const int*)klen_raw;
        int kv;
        if (ki[1] == 0) kv = (int)((const long long*)klen_raw)[t];
        else            kv = ki[t];
        s_klen[t] = kv;
    }
    __syncthreads();
    if (t < BB) {
        int c = 0;
        for (int s = 0; s < NS; s++) c += (s_sidx[s] < s_klen[t]) ? 1 : 0;
        g_mkl[t] = c;
    }
}

// ---------------------------------------------------------------------------
// Pre-round fp32 -> tf32-representable fp32 (cvt.rna). sel: 0=g_qr 1=g_wr 2=g_owr
// ---------------------------------------------------------------------------
__global__ void round_kernel(const float4* __restrict__ src, int n4, int sel)
{
    float4* dst = sel == 0 ? (float4*)g_qr : sel == 1 ? (float4*)g_wr : (float4*)g_owr;
    for (int i = blockIdx.x * blockDim.x + threadIdx.x; i < n4; i += gridDim.x * blockDim.x) {
        float4 v = src[i];
        v.x = tf32r(v.x); v.y = tf32r(v.y); v.z = tf32r(v.z); v.w = tf32r(v.w);
        dst[i] = v;
    }
}

// Gather sampled k/v rows and round: row = s*BB+b -> src row sidx[s]*BB+b
__global__ void gather_round_kernel(const float* __restrict__ k, const float* __restrict__ v)
{
    int row = blockIdx.x;                      // 0..1023
    int src = g_sidx[row >> 3] * BB + (row & 7);
    const float4* ks = (const float4*)(k + (size_t)src * DM);
    const float4* vs = (const float4*)(v + (size_t)src * DM);
    float4* kd = (float4*)(g_kg + (size_t)row * DM);
    float4* vd = (float4*)(g_vg + (size_t)row * DM);
    int t = threadIdx.x;                       // 256 threads, DM/4 = 256 chunks
    float4 a = ks[t];
    a.x = tf32r(a.x); a.y = tf32r(a.y); a.z = tf32r(a.z); a.w = tf32r(a.w);
    kd[t] = a;
    float4 b = vs[t];
    b.x = tf32r(b.x); b.y = tf32r(b.y); b.z = tf32r(b.z); b.w = tf32r(b.w);
    vd[t] = b;
}

// ---------------------------------------------------------------------------
// TF32 mma.sync GEMM:  C = A * W^T + bias.  Inputs PRE-ROUNDED to tf32.
// Block tile 128x128x32, 256 threads (8 warps, warp tile 32x64), double-
// buffered cp.async smem, no cvt in mainloop (bits fed straight to mma).
// __launch_bounds__(256,2) -> 2 CTA/SM -> 16 warps/SM.
// CMODE: 0 = out-proj (A=g_ctx, W=g_owr, C=param)
//        1 = q-proj   (A=g_qr,  W=g_wr,  scatter g_qp)
//        2 = kv-proj  (z: A=g_kg/g_vg, W=Wk/Wv, scatter g_kp/g_vp)
// ---------------------------------------------------------------------------
#define BKK 32
#define ROWPAD 36
#define A_STAGE (128 * ROWPAD)          // floats per stage buffer
static const int GEMM_SMEM = 4 * A_STAGE * 4;   // 73728 B

template <int CMODE>
__global__ void __launch_bounds__(256, 2)
tgemm_nt(const float* __restrict__ bias_ext, float* __restrict__ Cout)
{
    extern __shared__ float sm[];
    float* smA = sm;                      // [2][128][36]
    float* smB = sm + 2 * A_STAGE;        // [2][128][36]

    const int tid  = threadIdx.x;
    const int lane = tid & 31;
    const int wid  = tid >> 5;            // 0..7
    const int wm   = wid >> 1;            // warp row (4) -> 32 rows each
    const int wn   = wid & 1;             // warp col (2) -> 64 cols each
    const int g    = lane >> 2;           // 0..7
    const int tig  = lane & 3;            // 0..3

    const int bm = blockIdx.y * 128;
    const int bn = blockIdx.x * 128;

    const float* A; const float* W; const float* bias;
    int z = 0;
    if (CMODE == 0)      { A = g_ctx; W = g_owr; bias = bias_ext; }
    else if (CMODE == 1) { A = g_qr;  W = g_wr;  bias = bias_ext; }
    else {
        z = blockIdx.z;
        A = z ? g_vg : g_kg;
        W = g_wr + (size_t)(z + 1) * DM * DM;
        bias = bias_ext + (size_t)(z + 1) * DM;
    }

    // --- loader geometry: 256 threads, 4 float4 per operand per stage ---
    const int lrow = tid >> 3;            // 0..31 (row within 32-row slab)
    const int lc4  = (tid & 7) * 4;       // 0..28 (k offset)

    const float* aptr[4];
    const float* wptr[4];
#pragma unroll
    for (int j = 0; j < 4; j++) {
        int r = j * 32 + lrow;            // 0..127 row within tile
        aptr[j] = A + (size_t)(bm + r) * DM + lc4;
        wptr[j] = W + (size_t)(bn + r) * DM + lc4;
    }
    const uint32_t sdstA = smem_u32(smA + lrow * ROWPAD + lc4);
    const uint32_t sdstB = smem_u32(smB + lrow * ROWPAD + lc4);

    float4 acc[2][8];
#pragma unroll
    for (int i = 0; i < 2; i++)
#pragma unroll
        for (int j = 0; j < 8; j++) acc[i][j] = make_float4(0.f, 0.f, 0.f, 0.f);

    const int nk = DM / BKK;              // 32

    // prologue: stage 0
#pragma unroll
    for (int j = 0; j < 4; j++) {
        asm volatile("cp.async.cg.shared.global [%0], [%1], 16;\n"
                     :: "r"(sdstA + (uint32_t)(j * 32 * ROWPAD * 4)), "l"(aptr[j]));
        asm volatile("cp.async.cg.shared.global [%0], [%1], 16;\n"
                     :: "r"(sdstB + (uint32_t)(j * 32 * ROWPAD * 4)), "l"(wptr[j]));
    }
    asm volatile("cp.async.commit_group;\n");

    for (int kt = 0; kt < nk; kt++) {
        if (kt + 1 < nk) {
            uint32_t bofs = (uint32_t)(((kt + 1) & 1) * A_STAGE * 4);
            int gofs = (kt + 1) * BKK;
#pragma unroll
            for (int j = 0; j < 4; j++) {
                asm volatile("cp.async.cg.shared.global [%0], [%1], 16;\n"
                             :: "r"(sdstA + bofs + (uint32_t)(j * 32 * ROWPAD * 4)),
                                "l"(aptr[j] + gofs));
                asm volatile("cp.async.cg.shared.global [%0], [%1], 16;\n"
                             :: "r"(sdstB + bofs + (uint32_t)(j * 32 * ROWPAD * 4)),
                                "l"(wptr[j] + gofs));
            }
            asm volatile("cp.async.commit_group;\n");
            asm volatile("cp.async.wait_group 1;\n" ::: "memory");
        } else {
            asm volatile("cp.async.wait_group 0;\n" ::: "memory");
        }
        __syncthreads();

        const float* Ab = smA + (kt & 1) * A_STAGE;
        const float* Bb = smB + (kt & 1) * A_STAGE;

#pragma unroll
        for (int ks = 0; ks < 4; ks++) {
            const int k0 = ks * 8 + tig;
            uint32_t afr[2][4];
            uint32_t bfr[8][2];
#pragma unroll
            for (int mt = 0; mt < 2; mt++) {
                int r = wm * 32 + mt * 16 + g;
                afr[mt][0] = __float_as_uint(Ab[r * ROWPAD + k0]);
                afr[mt][1] = __float_as_uint(Ab[(r + 8) * ROWPAD + k0]);
                afr[mt][2] = __float_as_uint(Ab[r * ROWPAD + k0 + 4]);
                afr[mt][3] = __float_as_uint(Ab[(r + 8) * ROWPAD + k0 + 4]);
            }
#pragma unroll
            for (int nt = 0; nt < 8; nt++) {
                int n = wn * 64 + nt * 8 + g;
                bfr[nt][0] = __float_as_uint(Bb[n * ROWPAD + k0]);
                bfr[nt][1] = __float_as_uint(Bb[n * ROWPAD + k0 + 4]);
            }
#pragma unroll
            for (int mt = 0; mt < 2; mt++)
#pragma unroll
                for (int nt = 0; nt < 8; nt++)
                    mma_tf32(acc[mt][nt], afr[mt], bfr[nt]);
        }
        __syncthreads();
    }

    // --- epilogue ---
#pragma unroll
    for (int nt = 0; nt < 8; nt++) {
        int col = bn + wn * 64 + nt * 8 + tig * 2;
        float b0 = bias[col], b1 = bias[col + 1];
#pragma unroll
        for (int mt = 0; mt < 2; mt++) {
            int row = bm + wm * 32 + mt * 16 + g;
            float2 v0 = make_float2(acc[mt][nt].x + b0, acc[mt][nt].y + b1);
            float2 v1 = make_float2(acc[mt][nt].z + b0, acc[mt][nt].w + b1);
            if (CMODE == 0) {
                *(float2*)(Cout + (size_t)row * DM + col) = v0;
                *(float2*)(Cout + (size_t)(row + 8) * DM + col) = v1;
            } else if (CMODE == 1) {
                int h_ = col >> 6, d_ = col & 63;
                int i0 = row >> 3, b_ = row & 7;
                *(float2*)(g_qp + (((size_t)(b_ * NH + h_)) * LQ + i0) * DH + d_) = v0;
                int i1 = (row + 8) >> 3;   // b_ unchanged (+8 rows = +1 i)
                *(float2*)(g_qp + (((size_t)(b_ * NH + h_)) * LQ + i1) * DH + d_) = v1;
            } else {
                int h_ = col >> 6, d_ = col & 63;
                int s0 = row >> 3, b_ = row & 7;
                float* dst = z ? g_vp : g_kp;
                *(float2*)(dst + ((b_ * NH + h_) * NS + s0) * DH + d_) = v0;
                int s1 = (row + 8) >> 3;
                *(float2*)(dst + ((b_ * NH + h_) * NS + s1) * DH + d_) = v1;
            }
        }
    }
}

// ---------------------------------------------------------------------------
// Fused attention: grid (L/128, B*H), 128 threads; epilogue emits tf32-rounded
// ctx so the out-projection's hardware truncation is exact.
// ---------------------------------------------------------------------------
__global__ void __launch_bounds__(128)
attn_kernel()
{
    extern __shared__ float smemf[];
    float* s_kv = smemf;                       // NS*DH = 8192 floats
    float* s_sc = smemf + NS * DH;             // 128*129 floats
    int*   s_si = (int*)(smemf + NS * DH + 128 * 129);

    const int ti = threadIdx.x;
    const int bh = blockIdx.y;                // b*NH + h
    const int b  = bh >> 4;
    const int h  = bh & 15;
    const int qi = blockIdx.x * 128 + ti;

    s_si[ti] = g_sidx[ti];

    const float4* kp4 = (const float4*)(g_kp + (size_t)bh * NS * DH);
#pragma unroll
    for (int x = ti; x < NS * DH / 4; x += 128)
        ((float4*)s_kv)[x] = kp4[x];
    __syncthreads();

    const int mkl = g_mkl[b];
    int lo = 0, hi = NS;
    while (lo < hi) { int mid = (lo + hi) >> 1; if (s_si[mid] <= qi) lo = mid + 1; else hi = mid; }
    const int nv = min(mkl, lo);              // >= 1 always (sidx[0]==0)

    float qr[DH];
    const float4* qrow = (const float4*)(g_qp + ((size_t)bh * LQ + qi) * DH);
#pragma unroll
    for (int d4 = 0; d4 < DH / 4; d4++) {
        float4 t = qrow[d4];
        qr[4 * d4] = t.x; qr[4 * d4 + 1] = t.y; qr[4 * d4 + 2] = t.z; qr[4 * d4 + 3] = t.w;
    }

    float* myrow = s_sc + ti * 129;
    float m = -1e30f;
    for (int s = 0; s < nv; s++) {
        const float4* kr = (const float4*)(s_kv + s * DH);
        float dot = 0.f;
#pragma unroll
        for (int d4 = 0; d4 < DH / 4; d4++) {
            float4 kv = kr[d4];
            dot = fmaf(qr[4 * d4], kv.x, dot);
            dot = fmaf(qr[4 * d4 + 1], kv.y, dot);
            dot = fmaf(qr[4 * d4 + 2], kv.z, dot);
            dot = fmaf(qr[4 * d4 + 3], kv.w, dot);
        }
        dot *= 0.125f;                        // 1/sqrt(64)
        myrow[s] = dot;
        m = fmaxf(m, dot);
    }
    float sum = 0.f;
    for (int s = 0; s < nv; s++) {
        float p = __expf(myrow[s] - m);
        myrow[s] = p;
        sum += p;
    }
    const float inv = 1.0f / sum;
    __syncthreads();                          // everyone done reading kp

    const float4* vp4 = (const float4*)(g_vp + (size_t)bh * NS * DH);
#pragma unroll
    for (int x = ti; x < NS * DH / 4; x += 128)
        ((float4*)s_kv)[x] = vp4[x];
    __syncthreads();

    float acc[DH];
#pragma unroll
    for (int d = 0; d < DH; d++) acc[d] = 0.f;
    for (int s = 0; s < nv; s++) {
        float p = myrow[s];
        const float4* vr = (const float4*)(s_kv + s * DH);
#pragma unroll
        for (int d4 = 0; d4 < DH / 4; d4++) {
            float4 vv = vr[d4];
            acc[4 * d4]     = fmaf(p, vv.x, acc[4 * d4]);
            acc[4 * d4 + 1] = fmaf(p, vv.y, acc[4 * d4 + 1]);
            acc[4 * d4 + 2] = fmaf(p, vv.z, acc[4 * d4 + 2]);
            acc[4 * d4 + 3] = fmaf(p, vv.w, acc[4 * d4 + 3]);
        }
    }
    float4* crow = (float4*)(g_ctx + ((size_t)qi * BB + b) * DM + h * DH);
#pragma unroll
    for (int d4 = 0; d4 < DH / 4; d4++) {
        float4 o;
        o.x = tf32r(acc[4 * d4] * inv);     o.y = tf32r(acc[4 * d4 + 1] * inv);
        o.z = tf32r(acc[4 * d4 + 2] * inv); o.w = tf32r(acc[4 * d4 + 3] * inv);
        crow[d4] = o;
    }
}

static const int ATTN_SMEM = (NS * DH + 128 * 129) * 4 + NS * 4;  // 99328 B

extern "C" void kernel_launch(void* const* d_in, const int* in_sizes, int n_in,
                              void* d_out, int out_size)
{
    const float* q    = (const float*)d_in[0];
    const float* k    = (const float*)d_in[1];
    const float* v    = (const float*)d_in[2];
    const void*  klen = d_in[3];
    const void*  sidx = d_in[4];
    const float* ipw  = (const float*)d_in[5];   // [3D, D]
    const float* ipb  = (const float*)d_in[6];   // [3D]
    const float* ow   = (const float*)d_in[7];   // [D, D]
    const float* ob   = (const float*)d_in[8];   // [D]
    float* out = (float*)d_out;

    (void)in_sizes; (void)n_in; (void)out_size;

    cudaFuncSetAttribute(attn_kernel, cudaFuncAttributeMaxDynamicSharedMemorySize, ATTN_SMEM);
    cudaFuncSetAttribute(tgemm_nt<0>, cudaFuncAttributeMaxDynamicSharedMemorySize, GEMM_SMEM);
    cudaFuncSetAttribute(tgemm_nt<1>, cudaFuncAttributeMaxDynamicSharedMemorySize, GEMM_SMEM);
    cudaFuncSetAttribute(tgemm_nt<2>, cudaFuncAttributeMaxDynamicSharedMemorySize, GEMM_SMEM);

    setup_kernel<<<1, 128>>>(sidx, klen);

    // pre-round inputs to tf32-representable fp32
    gather_round_kernel<<<NS * BB, 256>>>(k, v);
    round_kernel<<<4096, 256>>>((const float4*)q,   (LQ * BB * DM) / 4, 0);
    round_kernel<<<1024, 256>>>((const float4*)ipw, (3 * DM * DM) / 4,  1);
    round_kernel<<<1024, 256>>>((const float4*)ow,  (DM * DM) / 4,      2);

    // k/v projections (merged, z selects k vs v): M = S*B = 1024
    tgemm_nt<2><<<dim3(DM / 128, (NS * BB) / 128, 2), 256, GEMM_SMEM>>>(ipb, nullptr);
    // q projection: M = L*B = 32768
    tgemm_nt<1><<<dim3(DM / 128, (LQ * BB) / 128), 256, GEMM_SMEM>>>(ipb, nullptr);
    // fused masked attention
    attn_kernel<<<dim3(LQ / 128, BB * NH), 128, ATTN_SMEM>>>();
    // output projection
    tgemm_nt<0><<<dim3(DM / 128, (LQ * BB) / 128), 256, GEMM_SMEM>>>(ob, out);
}